// round 2
// baseline (speedup 1.0000x reference)
#include <cuda_runtime.h>
#include <stdint.h>

typedef unsigned long long u64;
typedef unsigned int u32;

#define NLEV 5
#define CLSN 16
#define TOPK 1000
#define NTOT 785664
#define KTOT (NLEV * TOPK)     /* 5000 */
#define ROWS (KTOT * CLSN)     /* 80000 */
#define HBINS 65536
#define WCAP 4096
#define MAXD 4.135166556742356f

__device__ __constant__ int d_off[6] = {0, 589824, 737280, 774144, 783360, 785664};
__device__ __constant__ int d_len[5] = {589824, 147456, 36864, 9216, 2304};

struct Ptrs {
    const float* anc[NLEV];
    const float* cls[NLEV];
    const float* reg[NLEV];
};

// ---------------- scratch (static device globals; no allocation) ----------------
__device__ u32 g_ord[NTOT];
__device__ int g_hist[NLEV][HBINS];
__device__ u64 g_win[NLEV][WCAP];
__device__ int g_nwin[NLEV];
__device__ int g_thr[NLEV];
__device__ u32 g_sel[KTOT];

// ---------------- K0: zero histograms + counters ----------------
__global__ void k_reset() {
    int g = blockIdx.x * 256 + threadIdx.x;
    int* hb = &g_hist[0][0];
    for (int i = g; i < NLEV * HBINS; i += gridDim.x * 256) hb[i] = 0;
    if (g < NLEV) g_nwin[g] = 0;
}

// ---- K1: ruler = max over 16 logits -> ordered key; 16-bit global histogram ----
__global__ void k_ruler(Ptrs p) {
    int g = blockIdx.x * 256 + threadIdx.x;   // grid exactly covers NTOT

    int l = 0;
#pragma unroll
    for (int j = 1; j < NLEV; j++) l += (g >= d_off[j]);
    int i = g - d_off[l];

    const float4* c4 = (const float4*)(p.cls[l]) + (size_t)i * 4;
    float4 a = c4[0], b = c4[1], c = c4[2], d = c4[3];
    float m = fmaxf(fmaxf(fmaxf(a.x, a.y), fmaxf(a.z, a.w)),
                    fmaxf(fmaxf(b.x, b.y), fmaxf(b.z, b.w)));
    m = fmaxf(m, fmaxf(fmaxf(c.x, c.y), fmaxf(c.z, c.w)));
    m = fmaxf(m, fmaxf(fmaxf(d.x, d.y), fmaxf(d.z, d.w)));

    u32 u = __float_as_uint(m);
    u32 ord = (u & 0x80000000u) ? ~u : (u | 0x80000000u);  // monotonic
    g_ord[g] = ord;

    // warp-aggregated histogram add (all threads of a block share one level)
    u32 bin = ord >> 16;
    unsigned peers = __match_any_sync(0xFFFFFFFFu, bin);
    int leader = __ffs(peers) - 1;
    if ((threadIdx.x & 31) == leader)
        atomicAdd(&g_hist[l][bin], __popc(peers));  // no return -> RED
}

// ---- K2: per-level threshold bin: largest T with suffix_count(T) >= TOPK ----
__global__ void k_resolve() {
    int l = blockIdx.x;
    int t = threadIdx.x;               // 1024 threads
    const int CH = HBINS / 1024;       // 64 bins per thread
    __shared__ int csum[1024];
    __shared__ int s_cidx, s_sufnext;
    __shared__ int s_bins[64];

    int base = t * CH, s = 0;
#pragma unroll 4
    for (int j = 0; j < CH; j++) s += g_hist[l][base + j];
    csum[t] = s;
    __syncthreads();
    // suffix sum over chunks (Hillis-Steele, reversed)
    for (int off = 1; off < 1024; off <<= 1) {
        int v = csum[t];
        int add = (t + off < 1024) ? csum[t + off] : 0;
        __syncthreads();
        csum[t] = v + add;
        __syncthreads();
    }
    if (csum[t] >= TOPK && (t == 1023 || csum[t + 1] < TOPK)) {
        s_cidx = t;
        s_sufnext = (t == 1023) ? 0 : csum[t + 1];
    }
    __syncthreads();
    int cbase = s_cidx * CH;
    if (t < CH) s_bins[t] = g_hist[l][cbase + t];
    __syncthreads();
    if (t == 0) {
        int suf = s_sufnext, b = cbase + CH - 1;
        for (int j = CH - 1; j >= 0; j--) {
            suf += s_bins[j];
            b = cbase + j;
            if (suf >= TOPK) break;
        }
        g_thr[l] = b;
    }
}

// ---- K3: collect every key with top16 >= threshold (warp-aggregated) ----
__global__ void k_select() {
    int g = blockIdx.x * 256 + threadIdx.x;
    int l = 0;
#pragma unroll
    for (int j = 1; j < NLEV; j++) l += (g >= d_off[j]);
    u32 ord = g_ord[g];
    bool win = (ord >> 16) >= (u32)g_thr[l];
    unsigned mask = __ballot_sync(0xFFFFFFFFu, win);
    if (win) {
        int lane = threadIdx.x & 31;
        int leader = __ffs(mask) - 1;
        int rank = __popc(mask & ((1u << lane) - 1));
        int base = 0;
        if (lane == leader) base = atomicAdd(&g_nwin[l], __popc(mask));
        base = __shfl_sync(mask, base, leader);
        int w = base + rank;
        if (w < WCAP) g_win[l][w] = ((u64)ord << 32) | (u32)(g - d_off[l]);
    }
}

// ---- K4: exact rank select: ascending (~ord, idx) == (value desc, idx asc) ----
__global__ void k_rank() {
    __shared__ u64 s[WCAP];
    int l = blockIdx.x;
    int n = g_nwin[l];
    if (n > WCAP) n = WCAP;
    int t = threadIdx.x;               // 1024 threads
    for (int i = t; i < n; i += 1024)
        s[i] = g_win[l][i] ^ 0xFFFFFFFF00000000ULL;
    __syncthreads();
    for (int i = t; i < n; i += 1024) {
        u64 me = s[i];
        int rank = 0;
        int j = 0;
        for (; j + 4 <= n; j += 4) {
            rank += (s[j] < me) + (s[j + 1] < me) + (s[j + 2] < me) + (s[j + 3] < me);
        }
        for (; j < n; j++) rank += (s[j] < me);
        if (rank < TOPK) g_sel[l * TOPK + rank] = (u32)(me & 0xFFFFFFFFu);
    }
}

// ---- K5: gather, sigmoid, decode, tile x16 classes ----
__global__ void k_final(Ptrs p, float* __restrict__ out) {
    int r = blockIdx.x * 256 + threadIdx.x;
    if (r >= ROWS) return;
    int k = r >> 4;
    int c = r & 15;
    int l = k / TOPK;
    u32 idx = g_sel[k];
    if (idx >= (u32)d_len[l]) idx = 0;  // safety (never hit on valid data)

    float4 a4 = ((const float4*)p.anc[l])[idx];
    float4 r4 = ((const float4*)p.reg[l])[idx * 2];   // first 4 of the 8 reg values
    float score = p.cls[l][(size_t)idx * 16 + c];

    float w = a4.z - a4.x, h = a4.w - a4.y;
    float cx = a4.x + 0.5f * w, cy = a4.y + 0.5f * h;
    float pcx = cx + r4.x * w, pcy = cy + r4.y * h;
    float pw = w * expf(fminf(r4.z, MAXD));
    float ph = h * expf(fminf(r4.w, MAXD));
    float sg = 1.0f / (1.0f + expf(-score));

    float* o = out + (size_t)r * 6;
    o[0] = pcx - 0.5f * pw;
    o[1] = pcy - 0.5f * ph;
    o[2] = pcx + 0.5f * pw;
    o[3] = pcy + 0.5f * ph;
    o[4] = sg;
    o[5] = (float)(c + 1);
}

extern "C" void kernel_launch(void* const* d_in, const int* in_sizes, int n_in,
                              void* d_out, int out_size) {
    (void)in_sizes; (void)n_in; (void)out_size;
    Ptrs p;
    for (int l = 0; l < NLEV; l++) {
        p.anc[l] = (const float*)d_in[3 * l + 0];
        p.cls[l] = (const float*)d_in[3 * l + 1];
        p.reg[l] = (const float*)d_in[3 * l + 2];
    }

    k_reset<<<640, 256>>>();
    k_ruler<<<NTOT / 256, 256>>>(p);
    k_resolve<<<NLEV, 1024>>>();
    k_select<<<NTOT / 256, 256>>>();
    k_rank<<<NLEV, 1024>>>();
    k_final<<<(ROWS + 255) / 256, 256>>>(p, (float*)d_out);
}